// round 3
// baseline (speedup 1.0000x reference)
#include <cuda_runtime.h>
#include <cuda_bf16.h>
#include <math_constants.h>

// Problem constants
#define N_NODES 100000
#define N_EDGES 1600000
#define D_IN  64
#define D_HID 64
#define D_OUT 40

// ---------------------------------------------------------------------------
// Scratch (device globals — no runtime allocation allowed)
// ---------------------------------------------------------------------------
__device__ float g_dinv[N_NODES];                 // deg -> rsqrt(deg)
__device__ float g_H1  [(size_t)N_NODES * D_HID]; // X @ W1
__device__ float g_agg1[(size_t)N_NODES * D_HID]; // layer-1 aggregation
__device__ float g_H2  [(size_t)N_NODES * D_OUT]; // relu(agg1) @ W2

// ---------------------------------------------------------------------------
// 1) degree = 1 (self loop) + count of col occurrences
// ---------------------------------------------------------------------------
__global__ void k_init_deg() {
    int i = blockIdx.x * blockDim.x + threadIdx.x;
    if (i < N_NODES) g_dinv[i] = 1.0f;
}

__global__ void k_count_deg(const int* __restrict__ ei) {
    int e = blockIdx.x * blockDim.x + threadIdx.x;
    if (e < N_EDGES) {
        int col = ei[N_EDGES + e];
        atomicAdd(&g_dinv[col], 1.0f);
    }
}

__global__ void k_finalize_dinv() {
    int i = blockIdx.x * blockDim.x + threadIdx.x;
    if (i < N_NODES) g_dinv[i] = rsqrtf(g_dinv[i]);  // deg >= 1 always
}

// ---------------------------------------------------------------------------
// 2) H1 = X @ W1   (block = 4 rows x 64 cols, W1 in smem)
// ---------------------------------------------------------------------------
__global__ void k_gemm1(const float* __restrict__ x, const float* __restrict__ W) {
    __shared__ float Ws[D_IN * D_HID];   // 16 KB
    __shared__ float Xs[4][D_IN];
    int tid = threadIdx.x;
    for (int i = tid; i < D_IN * D_HID; i += 256) Ws[i] = W[i];
    int ty = tid >> 6, tx = tid & 63;
    int r = blockIdx.x * 4 + ty;
    if (r < N_NODES) Xs[ty][tx] = x[(size_t)r * D_IN + tx];
    __syncthreads();
    if (r < N_NODES) {
        float acc = 0.0f;
        #pragma unroll
        for (int k = 0; k < D_IN; k++) acc = fmaf(Xs[ty][k], Ws[k * D_HID + tx], acc);
        g_H1[(size_t)r * D_HID + tx] = acc;
    }
}

// ---------------------------------------------------------------------------
// 3) agg1[i] = H1[i] * dinv[i]^2 + b1   (self-loop term + bias)
// ---------------------------------------------------------------------------
__global__ void k_init_agg1(const float* __restrict__ b1) {
    size_t idx = (size_t)blockIdx.x * blockDim.x + threadIdx.x;
    if (idx < (size_t)N_NODES * D_HID) {
        int i = (int)(idx >> 6);
        int d = (int)(idx & 63);
        float di = g_dinv[i];
        g_agg1[idx] = g_H1[idx] * di * di + b1[d];
    }
}

// ---------------------------------------------------------------------------
// 4) edge scatter, d=64: warp per edge, lane -> float2 chunk, vector red
// ---------------------------------------------------------------------------
__global__ void k_scatter64(const int* __restrict__ ei) {
    int gtid = blockIdx.x * blockDim.x + threadIdx.x;
    int w = gtid >> 5;
    int lane = gtid & 31;
    if (w >= N_EDGES) return;
    int row = ei[w];
    int col = ei[N_EDGES + w];
    float nrm = g_dinv[row] * g_dinv[col];
    const float2* src = reinterpret_cast<const float2*>(g_H1 + (size_t)row * D_HID);
    float2 v = src[lane];
    float2* dst = reinterpret_cast<float2*>(g_agg1 + (size_t)col * D_HID) + lane;
    asm volatile("red.global.add.v2.f32 [%0], {%1, %2};"
                 :: "l"(dst), "f"(v.x * nrm), "f"(v.y * nrm) : "memory");
}

// ---------------------------------------------------------------------------
// 5) H2 = relu(agg1) @ W2   (block = 4 rows x 64 threads, 40 active cols)
// ---------------------------------------------------------------------------
__global__ void k_gemm2(const float* __restrict__ W) {
    __shared__ float Ws[D_HID * D_OUT];  // 10 KB
    __shared__ float Xs[4][D_HID];
    int tid = threadIdx.x;
    for (int i = tid; i < D_HID * D_OUT; i += 256) Ws[i] = W[i];
    int ty = tid >> 6, tx = tid & 63;
    int r = blockIdx.x * 4 + ty;
    if (r < N_NODES) Xs[ty][tx] = fmaxf(g_agg1[(size_t)r * D_HID + tx], 0.0f);
    __syncthreads();
    if (r < N_NODES && tx < D_OUT) {
        float acc = 0.0f;
        #pragma unroll
        for (int k = 0; k < D_HID; k++) acc = fmaf(Xs[ty][k], Ws[k * D_OUT + tx], acc);
        g_H2[(size_t)r * D_OUT + tx] = acc;
    }
}

// ---------------------------------------------------------------------------
// 6) out[i] = H2[i] * dinv[i]^2 + b2  (self loop; d_out is layer-2 accumulator)
// ---------------------------------------------------------------------------
__global__ void k_init_out(const float* __restrict__ b2, float* __restrict__ out) {
    size_t idx = (size_t)blockIdx.x * blockDim.x + threadIdx.x;
    if (idx < (size_t)N_NODES * D_OUT) {
        int i = (int)(idx / D_OUT);
        int d = (int)(idx % D_OUT);
        float di = g_dinv[i];
        out[idx] = g_H2[idx] * di * di + b2[d];
    }
}

// ---------------------------------------------------------------------------
// 7) edge scatter, d=40: warp per edge, 20 active float2 lanes
// ---------------------------------------------------------------------------
__global__ void k_scatter40(const int* __restrict__ ei, float* __restrict__ out) {
    int gtid = blockIdx.x * blockDim.x + threadIdx.x;
    int w = gtid >> 5;
    int lane = gtid & 31;
    if (w >= N_EDGES) return;
    int row = ei[w];
    int col = ei[N_EDGES + w];
    float nrm = g_dinv[row] * g_dinv[col];
    if (lane < 20) {
        const float2* src = reinterpret_cast<const float2*>(g_H2 + (size_t)row * D_OUT);
        float2 v = src[lane];
        float2* dst = reinterpret_cast<float2*>(out + (size_t)col * D_OUT) + lane;
        asm volatile("red.global.add.v2.f32 [%0], {%1, %2};"
                     :: "l"(dst), "f"(v.x * nrm), "f"(v.y * nrm) : "memory");
    }
}

// ---------------------------------------------------------------------------
// 8) log_softmax in place: warp per row (40 cols = lane + lane+32[<8])
// ---------------------------------------------------------------------------
__global__ void k_log_softmax(float* __restrict__ out) {
    int gtid = blockIdx.x * blockDim.x + threadIdx.x;
    int r = gtid >> 5;
    int lane = gtid & 31;
    if (r >= N_NODES) return;
    float* p = out + (size_t)r * D_OUT;
    float v0 = p[lane];
    float v1 = (lane < D_OUT - 32) ? p[32 + lane] : -CUDART_INF_F;
    float m = fmaxf(v0, v1);
    #pragma unroll
    for (int o = 16; o > 0; o >>= 1) m = fmaxf(m, __shfl_xor_sync(0xFFFFFFFFu, m, o));
    float s = expf(v0 - m) + ((lane < D_OUT - 32) ? expf(v1 - m) : 0.0f);
    #pragma unroll
    for (int o = 16; o > 0; o >>= 1) s += __shfl_xor_sync(0xFFFFFFFFu, s, o);
    float ls = m + logf(s);
    p[lane] = v0 - ls;
    if (lane < D_OUT - 32) p[32 + lane] = v1 - ls;
}

// ---------------------------------------------------------------------------
// Launch
// ---------------------------------------------------------------------------
extern "C" void kernel_launch(void* const* d_in, const int* in_sizes, int n_in,
                              void* d_out, int out_size) {
    const float* x  = (const float*)d_in[0];
    const int*   ei = (const int*)  d_in[1];
    const float* W1 = (const float*)d_in[2];
    const float* b1 = (const float*)d_in[3];
    const float* W2 = (const float*)d_in[4];
    const float* b2 = (const float*)d_in[5];
    float* out = (float*)d_out;

    const int T = 256;

    // degree / normalization
    k_init_deg   <<<(N_NODES + T - 1) / T, T>>>();
    k_count_deg  <<<(N_EDGES + T - 1) / T, T>>>(ei);
    k_finalize_dinv<<<(N_NODES + T - 1) / T, T>>>();

    // layer 1
    k_gemm1<<<(N_NODES + 3) / 4, T>>>(x, W1);
    {
        size_t tot = (size_t)N_NODES * D_HID;
        k_init_agg1<<<(unsigned)((tot + T - 1) / T), T>>>(b1);
    }
    {
        long long threads = (long long)N_EDGES * 32;
        k_scatter64<<<(unsigned)((threads + T - 1) / T), T>>>(ei);
    }

    // layer 2
    k_gemm2<<<(N_NODES + 3) / 4, T>>>(W2);
    {
        size_t tot = (size_t)N_NODES * D_OUT;
        k_init_out<<<(unsigned)((tot + T - 1) / T), T>>>(b2, out);
    }
    {
        long long threads = (long long)N_EDGES * 32;
        k_scatter40<<<(unsigned)((threads + T - 1) / T), T>>>(ei, out);
    }

    // log softmax (in place on d_out)
    {
        long long threads = (long long)N_NODES * 32;
        k_log_softmax<<<(unsigned)((threads + T - 1) / T), T>>>(out);
    }
}

// round 7
// speedup vs baseline: 2.5130x; 2.5130x over previous
#include <cuda_runtime.h>
#include <cuda_bf16.h>
#include <math_constants.h>

#define N_NODES 100000
#define N_EDGES 1600000
#define D_IN  64
#define D_HID 64
#define D_OUT 40

#define SCAN_B 512
#define NB ((N_NODES + SCAN_B - 1) / SCAN_B)   // 196

// ---------------------------------------------------------------------------
// Scratch (device globals — no runtime allocation allowed)
// ---------------------------------------------------------------------------
__device__ int   g_cnt   [N_NODES];            // in-degree (excl. self loop)
__device__ int   g_rowptr[N_NODES];            // exclusive prefix of cnt
__device__ int   g_cursor[N_NODES];            // bucket fill cursor
__device__ int   g_bsum  [NB];                 // per-block sums for scan
__device__ int   g_boff  [NB];                 // exclusive block offsets
__device__ int   g_esrc  [N_EDGES];            // edge sources sorted by col
__device__ float g_dinv  [N_NODES];
__device__ __align__(16) float g_H1pre[(size_t)N_NODES * D_HID]; // (X@W1)*dinv[row]
__device__ __align__(16) float g_B1   [(size_t)N_NODES * D_HID]; // relu(layer-1 out)
__device__ __align__(16) float g_H2pre[(size_t)N_NODES * D_OUT]; // (B1@W2)*dinv[row]

// ---------------------------------------------------------------------------
// CSR construction: zero → hist → reduce → scan(block sums) → scan+offsets
// ---------------------------------------------------------------------------
__global__ void k_zero_cnt() {
    int i = blockIdx.x * blockDim.x + threadIdx.x;
    if (i < N_NODES) g_cnt[i] = 0;
}

__global__ void k_hist(const int* __restrict__ ei) {
    int e = blockIdx.x * blockDim.x + threadIdx.x;
    if (e < N_EDGES) atomicAdd(&g_cnt[ei[N_EDGES + e]], 1);
}

__global__ void k_scan_reduce() {   // <<<NB, SCAN_B>>>
    __shared__ int ssum[SCAN_B / 32];
    int tid = threadIdx.x;
    int i = blockIdx.x * SCAN_B + tid;
    int v = (i < N_NODES) ? g_cnt[i] : 0;
    #pragma unroll
    for (int o = 16; o > 0; o >>= 1) v += __shfl_down_sync(0xFFFFFFFFu, v, o);
    if ((tid & 31) == 0) ssum[tid >> 5] = v;
    __syncthreads();
    if (tid < SCAN_B / 32) {
        v = ssum[tid];
        #pragma unroll
        for (int o = SCAN_B / 64; o > 0; o >>= 1)
            v += __shfl_down_sync(0xFFFFFFFFu, v, o);
        if (tid == 0) g_bsum[blockIdx.x] = v;
    }
}

__global__ void k_scan_blocks() {   // <<<1, 256>>>
    __shared__ int s[256];
    int t = threadIdx.x;
    int v = (t < NB) ? g_bsum[t] : 0;
    s[t] = v;
    __syncthreads();
    #pragma unroll
    for (int off = 1; off < 256; off <<= 1) {
        int a = (t >= off) ? s[t - off] : 0;
        __syncthreads();
        s[t] += a;
        __syncthreads();
    }
    if (t < NB) g_boff[t] = s[t] - v;   // exclusive
}

__global__ void k_scan_final() {    // <<<NB, SCAN_B>>>
    __shared__ int s[SCAN_B];
    int t = threadIdx.x;
    int i = blockIdx.x * SCAN_B + t;
    int v = (i < N_NODES) ? g_cnt[i] : 0;
    s[t] = v;
    __syncthreads();
    #pragma unroll
    for (int off = 1; off < SCAN_B; off <<= 1) {
        int a = (t >= off) ? s[t - off] : 0;
        __syncthreads();
        s[t] += a;
        __syncthreads();
    }
    if (i < N_NODES) {
        int excl = s[t] - v + g_boff[blockIdx.x];
        g_rowptr[i] = excl;
        g_cursor[i] = excl;
        g_dinv[i]   = rsqrtf((float)(v + 1));   // +1 self loop
    }
}

__global__ void k_bucket(const int* __restrict__ ei) {
    int e = blockIdx.x * blockDim.x + threadIdx.x;
    if (e < N_EDGES) {
        int row = ei[e];
        int col = ei[N_EDGES + e];
        int pos = atomicAdd(&g_cursor[col], 1);
        g_esrc[pos] = row;
    }
}

// ---------------------------------------------------------------------------
// GEMM1: H1pre[r] = (x[r] @ W1) * dinv[r].  32 rows/block, 8 rows/thread.
// ---------------------------------------------------------------------------
__global__ void k_gemm1(const float* __restrict__ x, const float* __restrict__ W) {
    __shared__ float4 Ws4[16][64];   // Ws4[kk][c] = W[4kk..4kk+3][c]  (16 KB)
    __shared__ float4 Xs4[32][16];   // row-major [32][64] floats      (8 KB)
    int tid = threadIdx.x;
    for (int idx = tid; idx < 16 * 64; idx += 256) {
        int kk = idx >> 6, c = idx & 63, k0 = kk * 4;
        Ws4[kk][c] = make_float4(W[(k0 + 0) * 64 + c], W[(k0 + 1) * 64 + c],
                                 W[(k0 + 2) * 64 + c], W[(k0 + 3) * 64 + c]);
    }
    int row0 = blockIdx.x * 32;
    float* Xf = (float*)Xs4;
    for (int idx = tid; idx < 32 * 64; idx += 256)
        Xf[idx] = x[(size_t)row0 * 64 + idx];
    __syncthreads();

    int tx = tid & 63, ty = tid >> 6;
    float acc[8] = {0, 0, 0, 0, 0, 0, 0, 0};
    #pragma unroll
    for (int kk = 0; kk < 16; kk++) {
        float4 w = Ws4[kk][tx];
        #pragma unroll
        for (int j = 0; j < 8; j++) {
            float4 xv = Xs4[ty * 8 + j][kk];
            acc[j] = fmaf(xv.x, w.x, fmaf(xv.y, w.y,
                     fmaf(xv.z, w.z, fmaf(xv.w, w.w, acc[j]))));
        }
    }
    #pragma unroll
    for (int j = 0; j < 8; j++) {
        int r = row0 + ty * 8 + j;
        g_H1pre[(size_t)r * D_HID + tx] = acc[j] * g_dinv[r];
    }
}

// ---------------------------------------------------------------------------
// Aggregation layer 1 (warp per node, gather, no atomics, 4-way MLP):
//   B1[i] = relu( dinv[i] * (H1pre[i] + sum_{e: col=i} H1pre[src]) + b1 )
// ---------------------------------------------------------------------------
__global__ void k_agg1(const float* __restrict__ b1) {
    int gtid = blockIdx.x * blockDim.x + threadIdx.x;
    int w = gtid >> 5, lane = gtid & 31;
    if (w >= N_NODES) return;
    const float2* __restrict__ H = (const float2*)g_H1pre;
    float2 acc = H[(size_t)w * 32 + lane];          // self loop
    int beg = g_rowptr[w], end = beg + g_cnt[w];
    for (int base = beg; base < end; base += 32) {
        int nn = min(32, end - base);
        int s = (lane < nn) ? g_esrc[base + lane] : 0;
        int t = 0;
        for (; t + 4 <= nn; t += 4) {
            int s0 = __shfl_sync(0xFFFFFFFFu, s, t);
            int s1 = __shfl_sync(0xFFFFFFFFu, s, t + 1);
            int s2 = __shfl_sync(0xFFFFFFFFu, s, t + 2);
            int s3 = __shfl_sync(0xFFFFFFFFu, s, t + 3);
            float2 v0 = H[(size_t)s0 * 32 + lane];
            float2 v1 = H[(size_t)s1 * 32 + lane];
            float2 v2 = H[(size_t)s2 * 32 + lane];
            float2 v3 = H[(size_t)s3 * 32 + lane];
            acc.x += (v0.x + v1.x) + (v2.x + v3.x);
            acc.y += (v0.y + v1.y) + (v2.y + v3.y);
        }
        for (; t < nn; t++) {
            int sj = __shfl_sync(0xFFFFFFFFu, s, t);
            float2 v = H[(size_t)sj * 32 + lane];
            acc.x += v.x; acc.y += v.y;
        }
    }
    float di = g_dinv[w];
    float2 b = ((const float2*)b1)[lane];
    float2 o;
    o.x = fmaxf(fmaf(acc.x, di, b.x), 0.0f);
    o.y = fmaxf(fmaf(acc.y, di, b.y), 0.0f);
    ((float2*)g_B1)[(size_t)w * 32 + lane] = o;
}

// ---------------------------------------------------------------------------
// GEMM2: H2pre[r] = (B1[r] @ W2) * dinv[r].  cols 0..39 active.
// ---------------------------------------------------------------------------
__global__ void k_gemm2(const float* __restrict__ W) {
    __shared__ float4 Ws4[16][40];   // 10 KB
    __shared__ float4 Xs4[32][16];   // 8 KB
    int tid = threadIdx.x;
    for (int idx = tid; idx < 16 * 40; idx += 256) {
        int kk = idx / 40, c = idx % 40, k0 = kk * 4;
        Ws4[kk][c] = make_float4(W[(k0 + 0) * 40 + c], W[(k0 + 1) * 40 + c],
                                 W[(k0 + 2) * 40 + c], W[(k0 + 3) * 40 + c]);
    }
    int row0 = blockIdx.x * 32;
    float* Xf = (float*)Xs4;
    for (int idx = tid; idx < 32 * 64; idx += 256)
        Xf[idx] = g_B1[(size_t)row0 * 64 + idx];
    __syncthreads();

    int tx = tid & 63, ty = tid >> 6;
    if (tx >= D_OUT) return;
    float acc[8] = {0, 0, 0, 0, 0, 0, 0, 0};
    #pragma unroll
    for (int kk = 0; kk < 16; kk++) {
        float4 w = Ws4[kk][tx];
        #pragma unroll
        for (int j = 0; j < 8; j++) {
            float4 xv = Xs4[ty * 8 + j][kk];
            acc[j] = fmaf(xv.x, w.x, fmaf(xv.y, w.y,
                     fmaf(xv.z, w.z, fmaf(xv.w, w.w, acc[j]))));
        }
    }
    #pragma unroll
    for (int j = 0; j < 8; j++) {
        int r = row0 + ty * 8 + j;
        g_H2pre[(size_t)r * D_OUT + tx] = acc[j] * g_dinv[r];
    }
}

// ---------------------------------------------------------------------------
// Aggregation layer 2 + bias + log-softmax fused (warp per node, 4-way MLP)
// ---------------------------------------------------------------------------
__global__ void k_agg2(const float* __restrict__ b2, float* __restrict__ out) {
    int gtid = blockIdx.x * blockDim.x + threadIdx.x;
    int w = gtid >> 5, lane = gtid & 31;
    if (w >= N_NODES) return;
    const float2* __restrict__ H = (const float2*)g_H2pre;  // row stride = 20 float2
    bool act = (lane < 20);
    float2 acc = make_float2(0.0f, 0.0f);
    if (act) acc = H[(size_t)w * 20 + lane];
    int beg = g_rowptr[w], end = beg + g_cnt[w];
    for (int base = beg; base < end; base += 32) {
        int nn = min(32, end - base);
        int s = (lane < nn) ? g_esrc[base + lane] : 0;
        int t = 0;
        for (; t + 4 <= nn; t += 4) {
            int s0 = __shfl_sync(0xFFFFFFFFu, s, t);
            int s1 = __shfl_sync(0xFFFFFFFFu, s, t + 1);
            int s2 = __shfl_sync(0xFFFFFFFFu, s, t + 2);
            int s3 = __shfl_sync(0xFFFFFFFFu, s, t + 3);
            if (act) {
                float2 v0 = H[(size_t)s0 * 20 + lane];
                float2 v1 = H[(size_t)s1 * 20 + lane];
                float2 v2 = H[(size_t)s2 * 20 + lane];
                float2 v3 = H[(size_t)s3 * 20 + lane];
                acc.x += (v0.x + v1.x) + (v2.x + v3.x);
                acc.y += (v0.y + v1.y) + (v2.y + v3.y);
            }
        }
        for (; t < nn; t++) {
            int sj = __shfl_sync(0xFFFFFFFFu, s, t);
            if (act) {
                float2 v = H[(size_t)sj * 20 + lane];
                acc.x += v.x; acc.y += v.y;
            }
        }
    }
    float di = g_dinv[w];
    float2 l = make_float2(-CUDART_INF_F, -CUDART_INF_F);
    if (act) {
        float2 b = ((const float2*)b2)[lane];
        l.x = fmaf(acc.x, di, b.x);
        l.y = fmaf(acc.y, di, b.y);
    }
    float m = fmaxf(l.x, l.y);
    #pragma unroll
    for (int o = 16; o > 0; o >>= 1) m = fmaxf(m, __shfl_xor_sync(0xFFFFFFFFu, m, o));
    float e = act ? (expf(l.x - m) + expf(l.y - m)) : 0.0f;
    #pragma unroll
    for (int o = 16; o > 0; o >>= 1) e += __shfl_xor_sync(0xFFFFFFFFu, e, o);
    float ls = m + logf(e);
    if (act) {
        float2* po = (float2*)out + (size_t)w * 20 + lane;
        *po = make_float2(l.x - ls, l.y - ls);
    }
}

// ---------------------------------------------------------------------------
// Launch
// ---------------------------------------------------------------------------
extern "C" void kernel_launch(void* const* d_in, const int* in_sizes, int n_in,
                              void* d_out, int out_size) {
    const float* x  = (const float*)d_in[0];
    const int*   ei = (const int*)  d_in[1];
    const float* W1 = (const float*)d_in[2];
    const float* b1 = (const float*)d_in[3];
    const float* W2 = (const float*)d_in[4];
    const float* b2 = (const float*)d_in[5];
    float* out = (float*)d_out;

    const int T = 256;

    // CSR build + dinv
    k_zero_cnt   <<<(N_NODES + T - 1) / T, T>>>();
    k_hist       <<<(N_EDGES + T - 1) / T, T>>>(ei);
    k_scan_reduce<<<NB, SCAN_B>>>();
    k_scan_blocks<<<1, 256>>>();
    k_scan_final <<<NB, SCAN_B>>>();
    k_bucket     <<<(N_EDGES + T - 1) / T, T>>>(ei);

    // layer 1
    k_gemm1<<<N_NODES / 32, 256>>>(x, W1);
    k_agg1 <<<(N_NODES * 32 + T - 1) / T, T>>>(b1);

    // layer 2 (+ fused log-softmax)
    k_gemm2<<<N_NODES / 32, 256>>>(W2);
    k_agg2 <<<(N_NODES * 32 + T - 1) / T, T>>>(b2, out);
}